// round 9
// baseline (speedup 1.0000x reference)
#include <cuda_runtime.h>
#include <cuda_bf16.h>
#include <cstdint>
#include <math.h>

// Problem constants (fixed by the reference setup_inputs)
#define BB 256   // batches
#define AA 64    // atoms
#define EE 128   // edges
#define KK 6     // neighbors
#define HH 256   // hidden

#define HBLK 64                   // H columns per CTA tile
#define ROW4 (HH / 4)             // 64 float4 per full rep row
#define TILES_PER_B (HH / HBLK)   // 4
#define NTILES (BB * TILES_PER_B) // 1024 CTAs, one tile each
#define NTHREADS 256
#define TILE_F4 (EE * HBLK / 4)   // 2048 float4 per tile

__global__ __launch_bounds__(NTHREADS)
void DirectedEdgeMessage_89885075571226_kernel(
    const float* __restrict__ rep,     // [B, E, H]
    const int*   __restrict__ pairs,   // [B, E, 2]
    const int*   __restrict__ nbrs,    // [B, E, K]
    const float* __restrict__ xyz,     // [B, A, 3]
    float*       __restrict__ out)     // [B, E, H]
{
    __shared__ float s_dist[EE];        // per-edge distance weight
    __shared__ int2  s_pair[EE * KK];   // {neighbor idx, weight bits} merged

    const int tid = threadIdx.x;
    const int b   = blockIdx.x >> 2;    // TILES_PER_B = 4
    const int hb  = blockIdx.x & 3;

    // ---- Phase A: distance weights ----
    if (tid < EE) {
        const int e  = tid;
        const int p0 = __ldg(&pairs[(b * EE + e) * 2 + 0]);
        const int p1 = __ldg(&pairs[(b * EE + e) * 2 + 1]);
        const float* x0 = xyz + ((size_t)b * AA + p0) * 3;
        const float* x1 = xyz + ((size_t)b * AA + p1) * 3;
        const float dx = __ldg(x0 + 0) - __ldg(x1 + 0);
        const float dy = __ldg(x0 + 1) - __ldg(x1 + 1);
        const float dz = __ldg(x0 + 2) - __ldg(x1 + 2);
        const float d2 = dx * dx + dy * dy + dz * dz;
        const float inv = 1.0f / d2;
        s_dist[e] = isinf(inv) ? 0.0f : inv;
    }
    __syncthreads();

    // ---- Phase B: merged (index, weight) pairs: 768 entries, 3 per thread ----
    {
        const int* nb = nbrs + (size_t)b * EE * KK;
        #pragma unroll
        for (int i = tid; i < EE * KK; i += NTHREADS) {
            const int nk = __ldg(&nb[i]);
            s_pair[i] = make_int2(nk * ROW4, __float_as_int(s_dist[nk]));
        }
    }
    __syncthreads();

    // ---- Gather: one LDS.64 + one independent LDG.128 per k, flat FMA tree ----
    const float4* __restrict__ repv =
        (const float4*)(rep + (size_t)b * EE * HH + hb * HBLK);
    float4* __restrict__ outv =
        (float4*)(out + (size_t)b * EE * HH + hb * HBLK);

    #pragma unroll
    for (int p = 0; p < TILE_F4 / NTHREADS; p++) {   // 8 iters
        const int i  = tid + p * NTHREADS;
        const int e  = i >> 4;                       // 16 lanes per edge row
        const int h4 = i & 15;                       // 256B contiguous per (e,k)
        const int2* pr = s_pair + e * KK;

        const int2 q0 = pr[0]; const int2 q1 = pr[1]; const int2 q2 = pr[2];
        const int2 q3 = pr[3]; const int2 q4 = pr[4]; const int2 q5 = pr[5];

        const float4 v0 = __ldg(&repv[(size_t)q0.x + h4]);
        const float4 v1 = __ldg(&repv[(size_t)q1.x + h4]);
        const float4 v2 = __ldg(&repv[(size_t)q2.x + h4]);
        const float4 v3 = __ldg(&repv[(size_t)q3.x + h4]);
        const float4 v4 = __ldg(&repv[(size_t)q4.x + h4]);
        const float4 v5 = __ldg(&repv[(size_t)q5.x + h4]);

        const float w0 = __int_as_float(q0.y), w1 = __int_as_float(q1.y);
        const float w2 = __int_as_float(q2.y), w3 = __int_as_float(q3.y);
        const float w4 = __int_as_float(q4.y), w5 = __int_as_float(q5.y);

        float4 a, c;                                 // two partial trees
        a.x = w0 * v0.x; a.y = w0 * v0.y; a.z = w0 * v0.z; a.w = w0 * v0.w;
        c.x = w1 * v1.x; c.y = w1 * v1.y; c.z = w1 * v1.z; c.w = w1 * v1.w;
        a.x = fmaf(w2, v2.x, a.x); a.y = fmaf(w2, v2.y, a.y);
        a.z = fmaf(w2, v2.z, a.z); a.w = fmaf(w2, v2.w, a.w);
        c.x = fmaf(w3, v3.x, c.x); c.y = fmaf(w3, v3.y, c.y);
        c.z = fmaf(w3, v3.z, c.z); c.w = fmaf(w3, v3.w, c.w);
        a.x = fmaf(w4, v4.x, a.x); a.y = fmaf(w4, v4.y, a.y);
        a.z = fmaf(w4, v4.z, a.z); a.w = fmaf(w4, v4.w, a.w);
        c.x = fmaf(w5, v5.x, c.x); c.y = fmaf(w5, v5.y, c.y);
        c.z = fmaf(w5, v5.z, c.z); c.w = fmaf(w5, v5.w, c.w);
        a.x += c.x; a.y += c.y; a.z += c.z; a.w += c.w;

        __stcs(&outv[(size_t)e * ROW4 + h4], a);     // bypass-ish store: keep L1 for rep
    }
}

extern "C" void kernel_launch(void* const* d_in, const int* in_sizes, int n_in,
                              void* d_out, int out_size)
{
    const float* rep   = (const float*)d_in[0];  // bond_representations [1,B,E,H]
    const int*   pairs = (const int*)  d_in[1];  // bond_pairs [B,E,2]
    const int*   nbrs  = (const int*)  d_in[2];  // bond_neighbors [B,E,K]
    const float* xyz   = (const float*)d_in[3];  // xyz [B,A,3]
    float*       out   = (float*)d_out;          // [1,B,E,H]

    DirectedEdgeMessage_89885075571226_kernel<<<NTILES, NTHREADS>>>(
        rep, pairs, nbrs, xyz, out);
}

// round 12
// speedup vs baseline: 1.1875x; 1.1875x over previous
#include <cuda_runtime.h>
#include <cuda_bf16.h>
#include <cstdint>
#include <math.h>

// Problem constants (fixed by the reference setup_inputs)
#define BB 256   // batches
#define AA 64    // atoms
#define EE 128   // edges
#define KK 6     // neighbors
#define HH 256   // hidden

#define NTHREADS 256
#define WPC 8                       // warps per CTA = edges per CTA
#define NCTAS (BB * EE / WPC)       // 4096 CTAs
#define R4 (HH / 4)                 // 64 float4 per rep row

__global__ __launch_bounds__(NTHREADS)
void DirectedEdgeMessage_89885075571226_kernel(
    const float* __restrict__ rep,     // [B, E, H]
    const int*   __restrict__ pairs,   // [B, E, 2]
    const int*   __restrict__ nbrs,    // [B, E, K]
    const float* __restrict__ xyz,     // [B, A, 3]
    float*       __restrict__ out)     // [B, E, H]
{
    const int wid = threadIdx.x >> 5;
    const int lid = threadIdx.x & 31;
    const int b   = blockIdx.x >> 4;                  // 16 CTAs per batch
    const int e   = ((blockIdx.x & 15) << 3) + wid;   // this warp's edge

    // ---- lanes 0..5: resolve (neighbor index, distance weight) ----
    int   nk = 0;
    float w  = 0.0f;
    if (lid < KK) {
        nk = __ldg(&nbrs[(b * EE + e) * KK + lid]);
        const int2 pr = __ldg((const int2*)&pairs[(b * EE + nk) * 2]);
        const float* x0 = xyz + (b * AA + pr.x) * 3;
        const float* x1 = xyz + (b * AA + pr.y) * 3;
        const float dx = __ldg(x0 + 0) - __ldg(x1 + 0);
        const float dy = __ldg(x0 + 1) - __ldg(x1 + 1);
        const float dz = __ldg(x0 + 2) - __ldg(x1 + 2);
        const float d2 = dx * dx + dy * dy + dz * dz;
        const float inv = 1.0f / d2;
        w = isinf(inv) ? 0.0f : inv;
    }

    // ---- broadcast the 6 (index, weight) pairs to all lanes ----
    const int   n0 = __shfl_sync(0xFFFFFFFFu, nk, 0);
    const int   n1 = __shfl_sync(0xFFFFFFFFu, nk, 1);
    const int   n2 = __shfl_sync(0xFFFFFFFFu, nk, 2);
    const int   n3 = __shfl_sync(0xFFFFFFFFu, nk, 3);
    const int   n4 = __shfl_sync(0xFFFFFFFFu, nk, 4);
    const int   n5 = __shfl_sync(0xFFFFFFFFu, nk, 5);
    const float w0 = __shfl_sync(0xFFFFFFFFu, w, 0);
    const float w1 = __shfl_sync(0xFFFFFFFFu, w, 1);
    const float w2 = __shfl_sync(0xFFFFFFFFu, w, 2);
    const float w3 = __shfl_sync(0xFFFFFFFFu, w, 3);
    const float w4 = __shfl_sync(0xFFFFFFFFu, w, 4);
    const float w5 = __shfl_sync(0xFFFFFFFFu, w, 5);

    // ---- gather: 12 fully independent LDG.128 per lane ----
    const float4* __restrict__ rep4 = (const float4*)rep + (size_t)b * (EE * R4);
    const int c0 = lid;         // float4 column 0..31
    const int c1 = lid + 32;    // float4 column 32..63

    const float4 a0 = __ldg(&rep4[n0 * R4 + c0]);
    const float4 b0 = __ldg(&rep4[n0 * R4 + c1]);
    const float4 a1 = __ldg(&rep4[n1 * R4 + c0]);
    const float4 b1 = __ldg(&rep4[n1 * R4 + c1]);
    const float4 a2 = __ldg(&rep4[n2 * R4 + c0]);
    const float4 b2 = __ldg(&rep4[n2 * R4 + c1]);
    const float4 a3 = __ldg(&rep4[n3 * R4 + c0]);
    const float4 b3 = __ldg(&rep4[n3 * R4 + c1]);
    const float4 a4 = __ldg(&rep4[n4 * R4 + c0]);
    const float4 b4 = __ldg(&rep4[n4 * R4 + c1]);
    const float4 a5 = __ldg(&rep4[n5 * R4 + c0]);
    const float4 b5 = __ldg(&rep4[n5 * R4 + c1]);

    // ---- flat FMA trees (two independent accumulator pairs) ----
    float4 accA, accB, tA, tB;
    accA.x = w0 * a0.x; accA.y = w0 * a0.y; accA.z = w0 * a0.z; accA.w = w0 * a0.w;
    accB.x = w0 * b0.x; accB.y = w0 * b0.y; accB.z = w0 * b0.z; accB.w = w0 * b0.w;
    tA.x   = w1 * a1.x; tA.y   = w1 * a1.y; tA.z   = w1 * a1.z; tA.w   = w1 * a1.w;
    tB.x   = w1 * b1.x; tB.y   = w1 * b1.y; tB.z   = w1 * b1.z; tB.w   = w1 * b1.w;

    accA.x = fmaf(w2, a2.x, accA.x); accA.y = fmaf(w2, a2.y, accA.y);
    accA.z = fmaf(w2, a2.z, accA.z); accA.w = fmaf(w2, a2.w, accA.w);
    accB.x = fmaf(w2, b2.x, accB.x); accB.y = fmaf(w2, b2.y, accB.y);
    accB.z = fmaf(w2, b2.z, accB.z); accB.w = fmaf(w2, b2.w, accB.w);
    tA.x   = fmaf(w3, a3.x, tA.x);   tA.y   = fmaf(w3, a3.y, tA.y);
    tA.z   = fmaf(w3, a3.z, tA.z);   tA.w   = fmaf(w3, a3.w, tA.w);
    tB.x   = fmaf(w3, b3.x, tB.x);   tB.y   = fmaf(w3, b3.y, tB.y);
    tB.z   = fmaf(w3, b3.z, tB.z);   tB.w   = fmaf(w3, b3.w, tB.w);

    accA.x = fmaf(w4, a4.x, accA.x); accA.y = fmaf(w4, a4.y, accA.y);
    accA.z = fmaf(w4, a4.z, accA.z); accA.w = fmaf(w4, a4.w, accA.w);
    accB.x = fmaf(w4, b4.x, accB.x); accB.y = fmaf(w4, b4.y, accB.y);
    accB.z = fmaf(w4, b4.z, accB.z); accB.w = fmaf(w4, b4.w, accB.w);
    tA.x   = fmaf(w5, a5.x, tA.x);   tA.y   = fmaf(w5, a5.y, tA.y);
    tA.z   = fmaf(w5, a5.z, tA.z);   tA.w   = fmaf(w5, a5.w, tA.w);
    tB.x   = fmaf(w5, b5.x, tB.x);   tB.y   = fmaf(w5, b5.y, tB.y);
    tB.z   = fmaf(w5, b5.z, tB.z);   tB.w   = fmaf(w5, b5.w, tB.w);

    accA.x += tA.x; accA.y += tA.y; accA.z += tA.z; accA.w += tA.w;
    accB.x += tB.x; accB.y += tB.y; accB.z += tB.z; accB.w += tB.w;

    // ---- store this edge's H row (fully coalesced) ----
    float4* __restrict__ out4 = (float4*)out + ((size_t)b * EE + e) * R4;
    out4[c0] = accA;
    out4[c1] = accB;
}

extern "C" void kernel_launch(void* const* d_in, const int* in_sizes, int n_in,
                              void* d_out, int out_size)
{
    const float* rep   = (const float*)d_in[0];  // bond_representations [1,B,E,H]
    const int*   pairs = (const int*)  d_in[1];  // bond_pairs [B,E,2]
    const int*   nbrs  = (const int*)  d_in[2];  // bond_neighbors [B,E,K]
    const float* xyz   = (const float*)d_in[3];  // xyz [B,A,3]
    float*       out   = (float*)d_out;          // [1,B,E,H]

    DirectedEdgeMessage_89885075571226_kernel<<<NCTAS, NTHREADS>>>(
        rep, pairs, nbrs, xyz, out);
}